// round 8
// baseline (speedup 1.0000x reference)
#include <cuda_runtime.h>
#include <cuda_bf16.h>
#include <math.h>
#include <stdint.h>

// ---------------- problem constants ----------------
#define MAX_NODES 100000
#define MAX_EDGES 2000000
#define D_IN  256
#define D_HID 256
#define D_CLS 64
#define KDIM  256   // K for both GEMMs

// ---------------- scratch (static, no allocs) ----------------
__device__ float g_h1  [(size_t)MAX_NODES * D_HID];
__device__ float g_agg1[(size_t)MAX_NODES * D_HID];
__device__ float g_h2  [(size_t)MAX_NODES * D_CLS];
__device__ float g_dinv[MAX_NODES];
__device__ int   g_cnt [MAX_NODES];
__device__ int   g_off [MAX_NODES];
__device__ int   g_cur [MAX_NODES];
__device__ int   g_srcsort[MAX_EDGES];
__device__ int   g_bsum[1024];
__device__ int   g_boff[1024];

// ================= CSR build (counting sort by dst) =================
__global__ void zero_cnt(int* cnt, int n) {
    int i = blockIdx.x * blockDim.x + threadIdx.x;
    if (i < n) cnt[i] = 0;
}

__global__ void count_dst(const int* __restrict__ dst, int* cnt, int E) {
    int e = blockIdx.x * blockDim.x + threadIdx.x;
    if (e < E) atomicAdd(&cnt[dst[e]], 1);
}

__global__ void dinv_k(const int* __restrict__ cnt, float* dinv, int n) {
    int i = blockIdx.x * blockDim.x + threadIdx.x;
    if (i < n) dinv[i] = rsqrtf((float)(cnt[i] + 1));  // +1 self loop
}

__global__ void block_sums(const int* __restrict__ cnt, int* bsum, int n) {
    __shared__ int sh[256];
    int i = blockIdx.x * 256 + threadIdx.x;
    sh[threadIdx.x] = (i < n) ? cnt[i] : 0;
    __syncthreads();
    for (int o = 128; o > 0; o >>= 1) {
        if (threadIdx.x < o) sh[threadIdx.x] += sh[threadIdx.x + o];
        __syncthreads();
    }
    if (threadIdx.x == 0) bsum[blockIdx.x] = sh[0];
}

__global__ void scan_bsums(const int* __restrict__ bsum, int* boff, int nb) {
    __shared__ int sh[1024];
    int t = threadIdx.x;
    int v = (t < nb) ? bsum[t] : 0;
    sh[t] = v;
    __syncthreads();
    for (int o = 1; o < 1024; o <<= 1) {
        int u = (t >= o) ? sh[t - o] : 0;
        __syncthreads();
        sh[t] += u;
        __syncthreads();
    }
    if (t < nb) boff[t] = sh[t] - v;  // exclusive
}

__global__ void scan_final(const int* __restrict__ cnt, const int* __restrict__ boff,
                           int* off, int* cur, int n) {
    __shared__ int sh[256];
    int i = blockIdx.x * 256 + threadIdx.x;
    int v = (i < n) ? cnt[i] : 0;
    sh[threadIdx.x] = v;
    __syncthreads();
    for (int o = 1; o < 256; o <<= 1) {
        int u = (threadIdx.x >= o) ? sh[threadIdx.x - o] : 0;
        __syncthreads();
        sh[threadIdx.x] += u;
        __syncthreads();
    }
    if (i < n) {
        int excl = boff[blockIdx.x] + sh[threadIdx.x] - v;
        off[i] = excl;
        cur[i] = excl;
    }
}

__global__ void place_edges(const int* __restrict__ src,
                            const int* __restrict__ dst,
                            int* cur, int* srcsort, int E) {
    int e = blockIdx.x * blockDim.x + threadIdx.x;
    if (e < E) {
        int d = dst[e];
        int pos = atomicAdd(&cur[d], 1);
        srcsort[pos] = src[e];
    }
}

// ================= 3xBF16 tensor-core GEMM with row-scale epilogue =================
// C[m,n] = rs[m] * sum_k A[m,k]*B[k,n], K=256, fp32 in/out.
// Markidis split: v = hi + lo (bf16); D += Ahi*Blo + Alo*Bhi + Ahi*Bhi.
// (hi,lo) packed in uint2 -> STS.64/LDS.64 (half the LSU instructions).
// Double-buffered smem: one __syncthreads per k-tile.

__device__ __forceinline__ uint2 split2_bf16(float2 v) {
    __nv_bfloat16 hx = __float2bfloat16(v.x);
    __nv_bfloat16 hy = __float2bfloat16(v.y);
    __nv_bfloat16 lx = __float2bfloat16(v.x - __bfloat162float(hx));
    __nv_bfloat16 ly = __float2bfloat16(v.y - __bfloat162float(hy));
    uint2 r;
    r.x = (uint32_t)__bfloat16_as_ushort(hx) | ((uint32_t)__bfloat16_as_ushort(hy) << 16);
    r.y = (uint32_t)__bfloat16_as_ushort(lx) | ((uint32_t)__bfloat16_as_ushort(ly) << 16);
    return r;
}

__device__ __forceinline__ void mma_bf16(float c[4], uint32_t a0, uint32_t a1,
                                         uint32_t a2, uint32_t a3,
                                         uint32_t b0, uint32_t b1) {
    asm volatile(
        "mma.sync.aligned.m16n8k16.row.col.f32.bf16.bf16.f32 "
        "{%0,%1,%2,%3}, {%4,%5,%6,%7}, {%8,%9}, {%0,%1,%2,%3};"
        : "+f"(c[0]), "+f"(c[1]), "+f"(c[2]), "+f"(c[3])
        : "r"(a0), "r"(a1), "r"(a2), "r"(a3), "r"(b0), "r"(b1));
}

// BM=128, BN=64, BK=16, 256 threads (8 warps 4x2), warp tile 32x32 (MT=2, NT=4).
__global__ __launch_bounds__(256)
void sgemm_bf16x3(const float* __restrict__ A,
                  const float* __restrict__ B,
                  float* __restrict__ C,
                  const float* __restrict__ rs,
                  int M, int N) {
    constexpr int BM = 128;
    constexpr int BN = 64;
    constexpr int BK = 16;
    constexpr int STR = 10;           // uint2 stride per row (8 words + pad 2)
    constexpr int MT = 2;
    constexpr int NT = 4;
    constexpr int AW = BM * 8 / 256;  // 4 packed words per thread
    constexpr int BW = BN * 8 / 256;  // 2

    __shared__ uint2 As[2][BM * STR];
    __shared__ uint2 Bs[2][BN * STR];

    const int tid  = threadIdx.x;
    const int wid  = tid >> 5;
    const int lane = tid & 31;
    const int g    = lane >> 2;
    const int tig  = lane & 3;
    const int row0 = blockIdx.y * BM;
    const int col0 = blockIdx.x * BN;
    const int warpM = (wid >> 1) * 32;
    const int warpN = (wid & 1) * 32;

    float2 pa[AW];
    float  pb[BW][2];

    // prefetch tile 0
#pragma unroll
    for (int j = 0; j < AW; j++) {
        int idx = tid + j * 256;
        int r = idx >> 3, w = idx & 7;
        int gr = row0 + r;
        pa[j] = (gr < M) ? *(const float2*)(A + (size_t)gr * KDIM + 2 * w)
                         : make_float2(0.0f, 0.0f);
    }
#pragma unroll
    for (int j = 0; j < BW; j++) {
        int idx = tid + j * 256;
        int nn = idx >> 3, w = idx & 7;
        pb[j][0] = B[(size_t)(2 * w)     * N + col0 + nn];
        pb[j][1] = B[(size_t)(2 * w + 1) * N + col0 + nn];
    }

    float acc[MT][NT][4];
#pragma unroll
    for (int mt = 0; mt < MT; mt++)
#pragma unroll
        for (int nt = 0; nt < NT; nt++)
#pragma unroll
            for (int i = 0; i < 4; i++) acc[mt][nt][i] = 0.0f;

#pragma unroll 1
    for (int k0 = 0; k0 < KDIM; k0 += BK) {
        const int stage = (k0 >> 4) & 1;
        // split + packed store of current tile
#pragma unroll
        for (int j = 0; j < AW; j++) {
            int idx = tid + j * 256;
            int r = idx >> 3, w = idx & 7;
            As[stage][r * STR + w] = split2_bf16(pa[j]);
        }
#pragma unroll
        for (int j = 0; j < BW; j++) {
            int idx = tid + j * 256;
            int nn = idx >> 3, w = idx & 7;
            Bs[stage][nn * STR + w] = split2_bf16(make_float2(pb[j][0], pb[j][1]));
        }
        __syncthreads();

        // prefetch next tile (hidden under MMAs)
        if (k0 + BK < KDIM) {
#pragma unroll
            for (int j = 0; j < AW; j++) {
                int idx = tid + j * 256;
                int r = idx >> 3, w = idx & 7;
                int gr = row0 + r;
                pa[j] = (gr < M) ? *(const float2*)(A + (size_t)gr * KDIM + k0 + BK + 2 * w)
                                 : make_float2(0.0f, 0.0f);
            }
#pragma unroll
            for (int j = 0; j < BW; j++) {
                int idx = tid + j * 256;
                int nn = idx >> 3, w = idx & 7;
                pb[j][0] = B[(size_t)(k0 + BK + 2 * w)     * N + col0 + nn];
                pb[j][1] = B[(size_t)(k0 + BK + 2 * w + 1) * N + col0 + nn];
            }
        }

        // fragment loads (packed hi/lo) + MMAs; one k16 step covers the tile
        uint2 av[MT][4];
#pragma unroll
        for (int mt = 0; mt < MT; mt++) {
            int r1 = (warpM + mt * 16 + g) * STR;
            int r2 = r1 + 8 * STR;
            av[mt][0] = As[stage][r1 + tig];
            av[mt][1] = As[stage][r2 + tig];
            av[mt][2] = As[stage][r1 + 4 + tig];
            av[mt][3] = As[stage][r2 + 4 + tig];
        }
        uint2 bv[NT][2];
#pragma unroll
        for (int nt = 0; nt < NT; nt++) {
            int base = (warpN + nt * 8 + g) * STR;
            bv[nt][0] = Bs[stage][base + tig];
            bv[nt][1] = Bs[stage][base + 4 + tig];
        }
#pragma unroll
        for (int mt = 0; mt < MT; mt++)
#pragma unroll
            for (int nt = 0; nt < NT; nt++) {
                mma_bf16(acc[mt][nt], av[mt][0].x, av[mt][1].x, av[mt][2].x, av[mt][3].x,
                         bv[nt][0].y, bv[nt][1].y);                       // hi * lo
                mma_bf16(acc[mt][nt], av[mt][0].y, av[mt][1].y, av[mt][2].y, av[mt][3].y,
                         bv[nt][0].x, bv[nt][1].x);                       // lo * hi
                mma_bf16(acc[mt][nt], av[mt][0].x, av[mt][1].x, av[mt][2].x, av[mt][3].x,
                         bv[nt][0].x, bv[nt][1].x);                       // hi * hi
            }
        // no trailing sync: next iteration writes the other stage; its barrier
        // orders this stage's reads before the rewrite two iterations later.
    }

    // epilogue: C[m,n] = rs[m] * acc
#pragma unroll
    for (int mt = 0; mt < MT; mt++) {
        int r1 = row0 + warpM + mt * 16 + g;
        int r2 = r1 + 8;
        float s1 = (r1 < M) ? rs[r1] : 0.0f;
        float s2 = (r2 < M) ? rs[r2] : 0.0f;
#pragma unroll
        for (int nt = 0; nt < NT; nt++) {
            int cc = col0 + warpN + nt * 8 + 2 * tig;
            if (r1 < M) {
                float2 v = make_float2(acc[mt][nt][0] * s1, acc[mt][nt][1] * s1);
                *(float2*)(C + (size_t)r1 * N + cc) = v;
            }
            if (r2 < M) {
                float2 v = make_float2(acc[mt][nt][2] * s2, acc[mt][nt][3] * s2);
                *(float2*)(C + (size_t)r2 * N + cc) = v;
            }
        }
    }
}

// ====== layer-1 aggregate: warp per node, fused bias+relu epilogue ======
__global__ void agg1_kernel(const float* __restrict__ h,
                            const int* __restrict__ srcsort,
                            const int* __restrict__ off,
                            const float* __restrict__ dinv,
                            const float* __restrict__ b1,
                            float* __restrict__ outA, int n, int E) {
    int node = blockIdx.x * (blockDim.x >> 5) + (threadIdx.x >> 5);
    if (node >= n) return;
    int lane = threadIdx.x & 31;

    const float4* hp = (const float4*)(h + (size_t)node * D_HID);
    float4 a0 = __ldg(hp + lane);
    float4 a1 = __ldg(hp + lane + 32);

    int e0 = off[node];
    int e1 = (node + 1 < n) ? off[node + 1] : E;
    for (int e = e0; e < e1; e++) {
        int s = srcsort[e];
        const float4* sp = (const float4*)(h + (size_t)s * D_HID);
        float4 v0 = __ldg(sp + lane);
        float4 v1 = __ldg(sp + lane + 32);
        a0.x += v0.x; a0.y += v0.y; a0.z += v0.z; a0.w += v0.w;
        a1.x += v1.x; a1.y += v1.y; a1.z += v1.z; a1.w += v1.w;
    }

    float di = dinv[node];
    const float4* bb = (const float4*)b1;
    float4 c0 = __ldg(bb + lane);
    float4 c1 = __ldg(bb + lane + 32);
    float4 r0, r1;
    r0.x = fmaxf(fmaf(a0.x, di, c0.x), 0.0f);
    r0.y = fmaxf(fmaf(a0.y, di, c0.y), 0.0f);
    r0.z = fmaxf(fmaf(a0.z, di, c0.z), 0.0f);
    r0.w = fmaxf(fmaf(a0.w, di, c0.w), 0.0f);
    r1.x = fmaxf(fmaf(a1.x, di, c1.x), 0.0f);
    r1.y = fmaxf(fmaf(a1.y, di, c1.y), 0.0f);
    r1.z = fmaxf(fmaf(a1.z, di, c1.z), 0.0f);
    r1.w = fmaxf(fmaf(a1.w, di, c1.w), 0.0f);
    float4* op = (float4*)(outA + (size_t)node * D_HID);
    op[lane]      = r0;
    op[lane + 32] = r1;
}

// ====== layer-2 aggregate: warp per node, fused bias + log_softmax ======
__global__ void agg2_kernel(const float* __restrict__ h,
                            const int* __restrict__ srcsort,
                            const int* __restrict__ off,
                            const float* __restrict__ dinv,
                            const float* __restrict__ b2,
                            float* __restrict__ out, int n, int E) {
    int node = blockIdx.x * (blockDim.x >> 5) + (threadIdx.x >> 5);
    if (node >= n) return;
    int lane = threadIdx.x & 31;

    const float2* hp = (const float2*)(h + (size_t)node * D_CLS);
    float2 a = __ldg(hp + lane);

    int e0 = off[node];
    int e1 = (node + 1 < n) ? off[node + 1] : E;
    for (int e = e0; e < e1; e++) {
        int s = srcsort[e];
        float2 v = __ldg(((const float2*)(h + (size_t)s * D_CLS)) + lane);
        a.x += v.x; a.y += v.y;
    }

    float di = dinv[node];
    float v0 = fmaf(a.x, di, __ldg(b2 + 2 * lane));
    float v1 = fmaf(a.y, di, __ldg(b2 + 2 * lane + 1));

    float m = fmaxf(v0, v1);
#pragma unroll
    for (int o = 16; o > 0; o >>= 1) m = fmaxf(m, __shfl_xor_sync(0xFFFFFFFFu, m, o));
    float s = __expf(v0 - m) + __expf(v1 - m);
#pragma unroll
    for (int o = 16; o > 0; o >>= 1) s += __shfl_xor_sync(0xFFFFFFFFu, s, o);
    float lse = m + __logf(s);

    float2* op = (float2*)(out + (size_t)node * D_CLS);
    op[lane] = make_float2(v0 - lse, v1 - lse);
}

extern "C" void kernel_launch(void* const* d_in, const int* in_sizes, int n_in,
                              void* d_out, int out_size) {
    const float* x   = (const float*)d_in[0];
    const int*   ei  = (const int*)d_in[1];   // JAX int64 request silently -> int32
    const float* W1  = (const float*)d_in[2];
    const float* b1  = (const float*)d_in[3];
    const float* W2  = (const float*)d_in[4];
    const float* b2  = (const float*)d_in[5];
    float*       out = (float*)d_out;

    const int n = in_sizes[0] / D_IN;
    const int E = in_sizes[1] / 2;
    const int* src = ei;
    const int* dst = ei + E;

    float *h1, *agg1, *h2, *dinv;
    int *cnt, *off, *cur, *srcsort, *bsum, *boff;
    cudaGetSymbolAddress((void**)&h1,     g_h1);
    cudaGetSymbolAddress((void**)&agg1,   g_agg1);
    cudaGetSymbolAddress((void**)&h2,     g_h2);
    cudaGetSymbolAddress((void**)&dinv,   g_dinv);
    cudaGetSymbolAddress((void**)&cnt,    g_cnt);
    cudaGetSymbolAddress((void**)&off,    g_off);
    cudaGetSymbolAddress((void**)&cur,    g_cur);
    cudaGetSymbolAddress((void**)&srcsort,g_srcsort);
    cudaGetSymbolAddress((void**)&bsum,   g_bsum);
    cudaGetSymbolAddress((void**)&boff,   g_boff);

    const int NB = (n + 255) / 256;  // <= 1024
    const int MB = (n + 127) / 128;

    // launches 1-3: degree counts + dinv (all GEMM1 needs)
    zero_cnt <<<NB, 256>>>(cnt, n);
    count_dst<<<(E + 255) / 256, 256>>>(dst, cnt, E);
    dinv_k   <<<NB, 256>>>(cnt, dinv, n);

    // launch 4: GEMM1 (lands in the ncu capture slot)
    sgemm_bf16x3<<<dim3(D_HID / 64, MB), 256>>>(x, W1, h1, dinv, n, D_HID);

    // CSR build (needed before agg1)
    block_sums <<<NB, 256>>>(cnt, bsum, n);
    scan_bsums <<<1, 1024>>>(bsum, boff, NB);
    scan_final <<<NB, 256>>>(cnt, boff, off, cur, n);
    place_edges<<<(E + 255) / 256, 256>>>(src, dst, cur, srcsort, E);

    agg1_kernel<<<(n + 7) / 8, 256>>>(h1, srcsort, off, dinv, b1, agg1, n, E);

    // ---- layer 2 ----
    sgemm_bf16x3<<<dim3(D_CLS / 64, MB), 256>>>(agg1, W2, h2, dinv, n, D_CLS);
    agg2_kernel<<<(n + 7) / 8, 256>>>(h2, srcsort, off, dinv, b2, out, n, E);
}

// round 9
// speedup vs baseline: 1.1176x; 1.1176x over previous
#include <cuda_runtime.h>
#include <cuda_bf16.h>
#include <math.h>
#include <stdint.h>

// ---------------- problem constants ----------------
#define MAX_NODES 100000
#define MAX_EDGES 2000000
#define D_IN  256
#define D_HID 256
#define D_CLS 64
#define KDIM  256   // K for both GEMMs

// ---------------- scratch (static, no allocs) ----------------
__device__ float g_h1  [(size_t)MAX_NODES * D_HID];
__device__ float g_agg1[(size_t)MAX_NODES * D_HID];
__device__ float g_h2  [(size_t)MAX_NODES * D_CLS];
__device__ float g_dinv[MAX_NODES];
__device__ int   g_cnt [MAX_NODES];
__device__ int   g_off [MAX_NODES];
__device__ int   g_cur [MAX_NODES];
__device__ int   g_srcsort[MAX_EDGES];
__device__ int   g_bsum[1024];
__device__ int   g_boff[1024];

// ================= CSR build (counting sort by dst) =================
__global__ void zero_cnt(int* cnt, int n) {
    int i = blockIdx.x * blockDim.x + threadIdx.x;
    if (i < n) cnt[i] = 0;
}

__global__ void count_dst(const int* __restrict__ dst, int* cnt, int E) {
    int e = blockIdx.x * blockDim.x + threadIdx.x;
    if (e < E) atomicAdd(&cnt[dst[e]], 1);
}

__global__ void dinv_k(const int* __restrict__ cnt, float* dinv, int n) {
    int i = blockIdx.x * blockDim.x + threadIdx.x;
    if (i < n) dinv[i] = rsqrtf((float)(cnt[i] + 1));  // +1 self loop
}

__global__ void block_sums(const int* __restrict__ cnt, int* bsum, int n) {
    __shared__ int sh[256];
    int i = blockIdx.x * 256 + threadIdx.x;
    sh[threadIdx.x] = (i < n) ? cnt[i] : 0;
    __syncthreads();
    for (int o = 128; o > 0; o >>= 1) {
        if (threadIdx.x < o) sh[threadIdx.x] += sh[threadIdx.x + o];
        __syncthreads();
    }
    if (threadIdx.x == 0) bsum[blockIdx.x] = sh[0];
}

__global__ void scan_bsums(const int* __restrict__ bsum, int* boff, int nb) {
    __shared__ int sh[1024];
    int t = threadIdx.x;
    int v = (t < nb) ? bsum[t] : 0;
    sh[t] = v;
    __syncthreads();
    for (int o = 1; o < 1024; o <<= 1) {
        int u = (t >= o) ? sh[t - o] : 0;
        __syncthreads();
        sh[t] += u;
        __syncthreads();
    }
    if (t < nb) boff[t] = sh[t] - v;  // exclusive
}

__global__ void scan_final(const int* __restrict__ cnt, const int* __restrict__ boff,
                           int* off, int* cur, int n) {
    __shared__ int sh[256];
    int i = blockIdx.x * 256 + threadIdx.x;
    int v = (i < n) ? cnt[i] : 0;
    sh[threadIdx.x] = v;
    __syncthreads();
    for (int o = 1; o < 256; o <<= 1) {
        int u = (threadIdx.x >= o) ? sh[threadIdx.x - o] : 0;
        __syncthreads();
        sh[threadIdx.x] += u;
        __syncthreads();
    }
    if (i < n) {
        int excl = boff[blockIdx.x] + sh[threadIdx.x] - v;
        off[i] = excl;
        cur[i] = excl;
    }
}

__global__ void place_edges(const int* __restrict__ src,
                            const int* __restrict__ dst,
                            int* cur, int* srcsort, int E) {
    int e = blockIdx.x * blockDim.x + threadIdx.x;
    if (e < E) {
        int d = dst[e];
        int pos = atomicAdd(&cur[d], 1);
        srcsort[pos] = src[e];
    }
}

// ================= 3xBF16 tensor-core GEMM with row-scale epilogue =================
// C[m,n] = rs[m] * sum_k A[m,k]*B[k,n], K=256, fp32 in/out.
// Markidis split: v = hi + lo (bf16); D += Ahi*Blo + Alo*Bhi + Ahi*Bhi.
// Separate hi/lo smem arrays, STR=12 words (48B rows: LDSM phases hit all 32
// banks exactly once). Fragment loads via ldmatrix.x4 (8 LDSM vs 32 LDS per tile).

__device__ __forceinline__ void split2_bf16(float2 v, uint32_t& hi, uint32_t& lo) {
    __nv_bfloat16 hx = __float2bfloat16(v.x);
    __nv_bfloat16 hy = __float2bfloat16(v.y);
    __nv_bfloat16 lx = __float2bfloat16(v.x - __bfloat162float(hx));
    __nv_bfloat16 ly = __float2bfloat16(v.y - __bfloat162float(hy));
    hi = (uint32_t)__bfloat16_as_ushort(hx) | ((uint32_t)__bfloat16_as_ushort(hy) << 16);
    lo = (uint32_t)__bfloat16_as_ushort(lx) | ((uint32_t)__bfloat16_as_ushort(ly) << 16);
}

__device__ __forceinline__ void ldsm_x4(uint32_t r[4], uint32_t addr) {
    asm volatile("ldmatrix.sync.aligned.m8n8.x4.shared.b16 {%0,%1,%2,%3}, [%4];"
                 : "=r"(r[0]), "=r"(r[1]), "=r"(r[2]), "=r"(r[3]) : "r"(addr));
}

__device__ __forceinline__ void mma_bf16(float c[4], const uint32_t a[4],
                                         uint32_t b0, uint32_t b1) {
    asm volatile(
        "mma.sync.aligned.m16n8k16.row.col.f32.bf16.bf16.f32 "
        "{%0,%1,%2,%3}, {%4,%5,%6,%7}, {%8,%9}, {%0,%1,%2,%3};"
        : "+f"(c[0]), "+f"(c[1]), "+f"(c[2]), "+f"(c[3])
        : "r"(a[0]), "r"(a[1]), "r"(a[2]), "r"(a[3]), "r"(b0), "r"(b1));
}

// BM=128, BN=64, BK=16, 256 threads (8 warps 4x2), warp tile 32x32 (MT=2, NT=4).
__global__ __launch_bounds__(256)
void sgemm_bf16x3(const float* __restrict__ A,
                  const float* __restrict__ B,
                  float* __restrict__ C,
                  const float* __restrict__ rs,
                  int M, int N) {
    constexpr int BM = 128;
    constexpr int BN = 64;
    constexpr int BK = 16;
    constexpr int STR = 12;           // words per row (8 data + 4 pad); 48B, 16B-aligned
    constexpr int MT = 2;
    constexpr int NT = 4;
    constexpr int AW = BM * 8 / 256;  // 4 packed words per thread
    constexpr int BW = BN * 8 / 256;  // 2

    __shared__ alignas(16) uint32_t As_hi[BM * STR], As_lo[BM * STR];
    __shared__ alignas(16) uint32_t Bs_hi[BN * STR], Bs_lo[BN * STR];

    const int tid  = threadIdx.x;
    const int wid  = tid >> 5;
    const int lane = tid & 31;
    const int g    = lane >> 2;
    const int tig  = lane & 3;
    const int q    = lane >> 3;       // ldmatrix group 0..3
    const int lr   = lane & 7;        // row within group
    const int row0 = blockIdx.y * BM;
    const int col0 = blockIdx.x * BN;
    const int warpM = (wid >> 1) * 32;
    const int warpN = (wid & 1) * 32;

    const uint32_t as_hi_b = (uint32_t)__cvta_generic_to_shared(As_hi);
    const uint32_t as_lo_b = (uint32_t)__cvta_generic_to_shared(As_lo);
    const uint32_t bs_hi_b = (uint32_t)__cvta_generic_to_shared(Bs_hi);
    const uint32_t bs_lo_b = (uint32_t)__cvta_generic_to_shared(Bs_lo);

    // ldmatrix per-lane byte offsets (constant across k-tiles)
    uint32_t a_off[MT], b_off[2];
#pragma unroll
    for (int mt = 0; mt < MT; mt++)
        a_off[mt] = (uint32_t)(((warpM + mt * 16 + (q & 1) * 8 + lr) * STR + (q >> 1) * 4) * 4);
#pragma unroll
    for (int p = 0; p < 2; p++)
        b_off[p] = (uint32_t)(((warpN + (2 * p + (q >> 1)) * 8 + lr) * STR + (q & 1) * 4) * 4);

    float2 pa[AW];
    float  pb[BW][2];

    // prefetch tile 0
#pragma unroll
    for (int j = 0; j < AW; j++) {
        int idx = tid + j * 256;
        int r = idx >> 3, w = idx & 7;
        int gr = row0 + r;
        pa[j] = (gr < M) ? *(const float2*)(A + (size_t)gr * KDIM + 2 * w)
                         : make_float2(0.0f, 0.0f);
    }
#pragma unroll
    for (int j = 0; j < BW; j++) {
        int idx = tid + j * 256;
        int nn = idx >> 3, w = idx & 7;
        pb[j][0] = B[(size_t)(2 * w)     * N + col0 + nn];
        pb[j][1] = B[(size_t)(2 * w + 1) * N + col0 + nn];
    }

    float acc[MT][NT][4];
#pragma unroll
    for (int mt = 0; mt < MT; mt++)
#pragma unroll
        for (int nt = 0; nt < NT; nt++)
#pragma unroll
            for (int i = 0; i < 4; i++) acc[mt][nt][i] = 0.0f;

#pragma unroll 1
    for (int k0 = 0; k0 < KDIM; k0 += BK) {
        // split + store current tile from regs
#pragma unroll
        for (int j = 0; j < AW; j++) {
            int idx = tid + j * 256;
            int r = idx >> 3, w = idx & 7;
            uint32_t hi, lo;
            split2_bf16(pa[j], hi, lo);
            As_hi[r * STR + w] = hi;
            As_lo[r * STR + w] = lo;
        }
#pragma unroll
        for (int j = 0; j < BW; j++) {
            int idx = tid + j * 256;
            int nn = idx >> 3, w = idx & 7;
            uint32_t hi, lo;
            split2_bf16(make_float2(pb[j][0], pb[j][1]), hi, lo);
            Bs_hi[nn * STR + w] = hi;
            Bs_lo[nn * STR + w] = lo;
        }
        __syncthreads();

        // prefetch next tile (hidden under MMAs)
        if (k0 + BK < KDIM) {
#pragma unroll
            for (int j = 0; j < AW; j++) {
                int idx = tid + j * 256;
                int r = idx >> 3, w = idx & 7;
                int gr = row0 + r;
                pa[j] = (gr < M) ? *(const float2*)(A + (size_t)gr * KDIM + k0 + BK + 2 * w)
                                 : make_float2(0.0f, 0.0f);
            }
#pragma unroll
            for (int j = 0; j < BW; j++) {
                int idx = tid + j * 256;
                int nn = idx >> 3, w = idx & 7;
                pb[j][0] = B[(size_t)(k0 + BK + 2 * w)     * N + col0 + nn];
                pb[j][1] = B[(size_t)(k0 + BK + 2 * w + 1) * N + col0 + nn];
            }
        }

        // fragment loads via ldmatrix.x4
        uint32_t a_hi[MT][4], a_lo[MT][4];
#pragma unroll
        for (int mt = 0; mt < MT; mt++) {
            ldsm_x4(a_hi[mt], as_hi_b + a_off[mt]);
            ldsm_x4(a_lo[mt], as_lo_b + a_off[mt]);
        }
        uint32_t b_hi[2][4], b_lo[2][4];  // [pair][nt0.b0, nt0.b1, nt1.b0, nt1.b1]
#pragma unroll
        for (int p = 0; p < 2; p++) {
            ldsm_x4(b_hi[p], bs_hi_b + b_off[p]);
            ldsm_x4(b_lo[p], bs_lo_b + b_off[p]);
        }

#pragma unroll
        for (int mt = 0; mt < MT; mt++)
#pragma unroll
            for (int nt = 0; nt < NT; nt++) {
                int p = nt >> 1, o = (nt & 1) * 2;
                mma_bf16(acc[mt][nt], a_hi[mt], b_lo[p][o], b_lo[p][o + 1]);  // hi*lo
                mma_bf16(acc[mt][nt], a_lo[mt], b_hi[p][o], b_hi[p][o + 1]);  // lo*hi
                mma_bf16(acc[mt][nt], a_hi[mt], b_hi[p][o], b_hi[p][o + 1]);  // hi*hi
            }
        __syncthreads();
    }

    // epilogue: C[m,n] = rs[m] * acc
#pragma unroll
    for (int mt = 0; mt < MT; mt++) {
        int r1 = row0 + warpM + mt * 16 + g;
        int r2 = r1 + 8;
        float s1 = (r1 < M) ? rs[r1] : 0.0f;
        float s2 = (r2 < M) ? rs[r2] : 0.0f;
#pragma unroll
        for (int nt = 0; nt < NT; nt++) {
            int cc = col0 + warpN + nt * 8 + 2 * tig;
            if (r1 < M) {
                float2 v = make_float2(acc[mt][nt][0] * s1, acc[mt][nt][1] * s1);
                *(float2*)(C + (size_t)r1 * N + cc) = v;
            }
            if (r2 < M) {
                float2 v = make_float2(acc[mt][nt][2] * s2, acc[mt][nt][3] * s2);
                *(float2*)(C + (size_t)r2 * N + cc) = v;
            }
        }
    }
}

// ====== layer-1 aggregate: warp per node, fused bias+relu epilogue ======
__global__ void agg1_kernel(const float* __restrict__ h,
                            const int* __restrict__ srcsort,
                            const int* __restrict__ off,
                            const float* __restrict__ dinv,
                            const float* __restrict__ b1,
                            float* __restrict__ outA, int n, int E) {
    int node = blockIdx.x * (blockDim.x >> 5) + (threadIdx.x >> 5);
    if (node >= n) return;
    int lane = threadIdx.x & 31;

    const float4* hp = (const float4*)(h + (size_t)node * D_HID);
    float4 a0 = __ldg(hp + lane);
    float4 a1 = __ldg(hp + lane + 32);

    int e0 = off[node];
    int e1 = (node + 1 < n) ? off[node + 1] : E;
    for (int e = e0; e < e1; e++) {
        int s = srcsort[e];
        const float4* sp = (const float4*)(h + (size_t)s * D_HID);
        float4 v0 = __ldg(sp + lane);
        float4 v1 = __ldg(sp + lane + 32);
        a0.x += v0.x; a0.y += v0.y; a0.z += v0.z; a0.w += v0.w;
        a1.x += v1.x; a1.y += v1.y; a1.z += v1.z; a1.w += v1.w;
    }

    float di = dinv[node];
    const float4* bb = (const float4*)b1;
    float4 c0 = __ldg(bb + lane);
    float4 c1 = __ldg(bb + lane + 32);
    float4 r0, r1;
    r0.x = fmaxf(fmaf(a0.x, di, c0.x), 0.0f);
    r0.y = fmaxf(fmaf(a0.y, di, c0.y), 0.0f);
    r0.z = fmaxf(fmaf(a0.z, di, c0.z), 0.0f);
    r0.w = fmaxf(fmaf(a0.w, di, c0.w), 0.0f);
    r1.x = fmaxf(fmaf(a1.x, di, c1.x), 0.0f);
    r1.y = fmaxf(fmaf(a1.y, di, c1.y), 0.0f);
    r1.z = fmaxf(fmaf(a1.z, di, c1.z), 0.0f);
    r1.w = fmaxf(fmaf(a1.w, di, c1.w), 0.0f);
    float4* op = (float4*)(outA + (size_t)node * D_HID);
    op[lane]      = r0;
    op[lane + 32] = r1;
}

// ====== layer-2 aggregate: warp per node, fused bias + log_softmax ======
__global__ void agg2_kernel(const float* __restrict__ h,
                            const int* __restrict__ srcsort,
                            const int* __restrict__ off,
                            const float* __restrict__ dinv,
                            const float* __restrict__ b2,
                            float* __restrict__ out, int n, int E) {
    int node = blockIdx.x * (blockDim.x >> 5) + (threadIdx.x >> 5);
    if (node >= n) return;
    int lane = threadIdx.x & 31;

    const float2* hp = (const float2*)(h + (size_t)node * D_CLS);
    float2 a = __ldg(hp + lane);

    int e0 = off[node];
    int e1 = (node + 1 < n) ? off[node + 1] : E;
    for (int e = e0; e < e1; e++) {
        int s = srcsort[e];
        float2 v = __ldg(((const float2*)(h + (size_t)s * D_CLS)) + lane);
        a.x += v.x; a.y += v.y;
    }

    float di = dinv[node];
    float v0 = fmaf(a.x, di, __ldg(b2 + 2 * lane));
    float v1 = fmaf(a.y, di, __ldg(b2 + 2 * lane + 1));

    float m = fmaxf(v0, v1);
#pragma unroll
    for (int o = 16; o > 0; o >>= 1) m = fmaxf(m, __shfl_xor_sync(0xFFFFFFFFu, m, o));
    float s = __expf(v0 - m) + __expf(v1 - m);
#pragma unroll
    for (int o = 16; o > 0; o >>= 1) s += __shfl_xor_sync(0xFFFFFFFFu, s, o);
    float lse = m + __logf(s);

    float2* op = (float2*)(out + (size_t)node * D_CLS);
    op[lane] = make_float2(v0 - lse, v1 - lse);
}

extern "C" void kernel_launch(void* const* d_in, const int* in_sizes, int n_in,
                              void* d_out, int out_size) {
    const float* x   = (const float*)d_in[0];
    const int*   ei  = (const int*)d_in[1];   // JAX int64 request silently -> int32
    const float* W1  = (const float*)d_in[2];
    const float* b1  = (const float*)d_in[3];
    const float* W2  = (const float*)d_in[4];
    const float* b2  = (const float*)d_in[5];
    float*       out = (float*)d_out;

    const int n = in_sizes[0] / D_IN;
    const int E = in_sizes[1] / 2;
    const int* src = ei;
    const int* dst = ei + E;

    float *h1, *agg1, *h2, *dinv;
    int *cnt, *off, *cur, *srcsort, *bsum, *boff;
    cudaGetSymbolAddress((void**)&h1,     g_h1);
    cudaGetSymbolAddress((void**)&agg1,   g_agg1);
    cudaGetSymbolAddress((void**)&h2,     g_h2);
    cudaGetSymbolAddress((void**)&dinv,   g_dinv);
    cudaGetSymbolAddress((void**)&cnt,    g_cnt);
    cudaGetSymbolAddress((void**)&off,    g_off);
    cudaGetSymbolAddress((void**)&cur,    g_cur);
    cudaGetSymbolAddress((void**)&srcsort,g_srcsort);
    cudaGetSymbolAddress((void**)&bsum,   g_bsum);
    cudaGetSymbolAddress((void**)&boff,   g_boff);

    const int NB = (n + 255) / 256;  // <= 1024
    const int MB = (n + 127) / 128;

    // launches 1-3: degree counts + dinv (all GEMM1 needs)
    zero_cnt <<<NB, 256>>>(cnt, n);
    count_dst<<<(E + 255) / 256, 256>>>(dst, cnt, E);
    dinv_k   <<<NB, 256>>>(cnt, dinv, n);

    // launch 4: GEMM1 (lands in the ncu capture slot)
    sgemm_bf16x3<<<dim3(D_HID / 64, MB), 256>>>(x, W1, h1, dinv, n, D_HID);

    // CSR build (needed before agg1)
    block_sums <<<NB, 256>>>(cnt, bsum, n);
    scan_bsums <<<1, 1024>>>(bsum, boff, NB);
    scan_final <<<NB, 256>>>(cnt, boff, off, cur, n);
    place_edges<<<(E + 255) / 256, 256>>>(src, dst, cur, srcsort, E);

    agg1_kernel<<<(n + 7) / 8, 256>>>(h1, srcsort, off, dinv, b1, agg1, n, E);

    // ---- layer 2 ----
    sgemm_bf16x3<<<dim3(D_CLS / 64, MB), 256>>>(agg1, W2, h2, dinv, n, D_CLS);
    agg2_kernel<<<(n + 7) / 8, 256>>>(h2, srcsort, off, dinv, b2, out, n, E);
}